// round 11
// baseline (speedup 1.0000x reference)
#include <cuda_runtime.h>
#include <math.h>

// -------------------------------------------------------------------------
// VectorizedConstantVelocityModel — GB300 sm_103a, round 11
//
// Base = R10 (best: 512 thr x 2 CTAs/SM, 2-row register tiling, cheap
// transcendentals, eps-fold, t0==0 specialization, evt prefetch, fused
// last-block reduction), plus:
//  * fine-grained snake units: (row-pair, j-half) -> 4096 units over 296
//    blocks (was 2048) -> work spread ~4% -> ~1%.
//  * #pragma unroll 2 inner loop: 4 independent pair chains / thread,
//    halved loop overhead.
// -------------------------------------------------------------------------

#define THREADS 512
#define GRID    296

__device__ double       g_part[GRID];
__device__ unsigned int g_flag = 0;

__device__ __forceinline__ float ex2f(float x) {
    float r; asm("ex2.approx.f32 %0,%1;" : "=f"(r) : "f"(x)); return r;
}
__device__ __forceinline__ float rcpf(float x) {
    float r; asm("rcp.approx.f32 %0,%1;" : "=f"(r) : "f"(x)); return r;
}

#define L2E 1.4426950408889634f

// erf on [-0.85, 0.85]: odd Taylor/minimax, abs err ~2e-5, no MUFU.
__device__ __forceinline__ float erf_small(float x)
{
    const float u = x * x;
    float p = fmaf(0.0052239776f, u, -0.0268661706f);
    p = fmaf(p, u, 0.1128379167f);
    p = fmaf(p, u, -0.3761263890f);
    p = fmaf(p, u, 1.1283791671f);
    return x * p;
}

// erf for any x: A&S 7.1.25 (3-term), abs err ~2.5e-5, auto-saturating.
__device__ __forceinline__ float erf_any(float x)
{
    const float t = rcpf(fmaf(0.47047f, fabsf(x), 1.0f));   // MUFU.RCP
    float q = fmaf(0.7478556f, t, -0.0958798f);
    q = fmaf(q, t, 0.3480242f);
    q = q * t;
    const float ex = ex2f((-L2E * x) * x);   // exp(-x^2)
    return copysignf(fmaf(-q, ex, 1.0f), x);
}

// One pair (without sqrt(pi)/2): isq * exp(b + h^2 - c) * (erf(xu) - erf(xl))
template <bool T0Z>
__device__ __forceinline__ float pair_term(const float4 a4, const float4 b4,
                                           float bL2E, float t0, float tn)
{
    const float dzx = a4.x - b4.x;
    const float dzy = a4.y - b4.y;
    const float dvx = a4.z - b4.z;
    const float dvy = a4.w - b4.w;
    const float as  = fmaf(dvx, dvx, fmaf(dvy, dvy, 1e-10f));  // |dv|^2 + eps
    const float bbh = fmaf(dzx, dvx, dzy * dvy);               // dz.dv
    const float c   = fmaf(dzx, dzx, dzy * dzy);
    const float isq = rsqrtf(as);                              // MUFU.RSQ
    const float sqa = as * isq;
    const float h   = bbh * isq;                               // |h| <= 0.71
    const float t1   = fmaf(c, -L2E, bL2E);                    // (b - c)*log2e
    const float earg = fmaf(h * h, L2E, t1);
    const float eE   = ex2f(earg);                             // exp(b+h^2-c)
    const float xu = fmaf(sqa, tn, h);
    const float xl = T0Z ? h : fmaf(sqa, t0, h);
    const float dif = erf_any(xu) - erf_small(xl);
    return (isq * eE) * dif;
}

template <bool T0Z>
__device__ __forceinline__ float pair_loop(const float4* __restrict__ zv,
                                           int N, int bid, int tid,
                                           float bL2E, float t0, float tn)
{
    float acc = 0.0f;
    const int NV = N;   // 4096 units: (N/2 row-pairs) x (2 j-halves)

    for (int k = 0; ; k++) {
        const int v = (k & 1) ? ((k + 1) * GRID - 1 - bid) : (k * GRID + bid);
        if (v >= NV) break;

        const int u    = v >> 1;
        const int half = v & 1;
        const int i0   = 2 * u;
        const float4 a0 = zv[i0];
        const float4 a1 = zv[i0 + 1];

        if (half == 0 && tid == 0)   // boundary pair (i0, i0+1), once per u
            acc += pair_term<T0Z>(a0, a1, bL2E, t0, tn);

        #pragma unroll 2
        for (int j = i0 + 2 + half * THREADS + tid; j < N; j += 2 * THREADS) {
            const float4 b4 = zv[j];
            acc += pair_term<T0Z>(a0, b4, bL2E, t0, tn);
            acc += pair_term<T0Z>(a1, b4, bL2E, t0, tn);
        }
    }
    return acc;
}

__global__ __launch_bounds__(THREADS, 2)
void fused_kernel(const float* __restrict__ data,
                  const float* __restrict__ z0, const float* __restrict__ v0,
                  const float* __restrict__ t0p, const float* __restrict__ tnp,
                  const float* __restrict__ betap,
                  int N, int M, float* __restrict__ out)
{
    extern __shared__ float4 zv[];   // (zx, zy, vx, vy)
    const int tid = threadIdx.x;
    const int bid = blockIdx.x;

    const float t0 = t0p[0];
    const float tn = tnp[0];
    const float b  = betap[0];
    const float bL2E = b * L2E;

    // ---- prefetch this thread's event triple (<=1 event/thread here) ----
    const int k0 = bid * THREADS + tid;
    float efi = 0.0f, efj = 0.0f, eft = 0.0f;
    const bool has_evt = (k0 < M);
    if (has_evt) {
        efi = data[3 * k0 + 0];
        efj = data[3 * k0 + 1];
        eft = data[3 * k0 + 2];
    }

    // ---- build smem tile ----
    {
        const float2* z2 = (const float2*)z0;
        const float2* v2 = (const float2*)v0;
        for (int k = tid; k < N; k += THREADS) {
            const float2 z = z2[k], v = v2[k];
            zv[k] = make_float4(z.x, z.y, v.x, v.y);
        }
    }
    __syncthreads();

    // ---- pair term (dominant) ----
    float acc;
    if (t0 == 0.0f) acc = pair_loop<true >(zv, N, bid, tid, bL2E, t0, tn);
    else            acc = pair_loop<false>(zv, N, bid, tid, bL2E, t0, tn);

    // ---- event term (prefetched data, smem tile still resident) ----
    float evt = 0.0f;
    if (has_evt) {
        const int i = (int)efi;
        const int j = (int)efj;
        const float4 pi = zv[i];
        const float4 pj = zv[j];
        const float dx = fmaf(pi.z - pj.z, eft, pi.x - pj.x);
        const float dy = fmaf(pi.w - pj.w, eft, pi.y - pj.y);
        evt = b - fmaf(dx, dx, dy * dy);
    }
    for (int k = k0 + GRID * THREADS; k < M; k += GRID * THREADS) {
        const int   i = (int)data[3 * k + 0];
        const int   j = (int)data[3 * k + 1];
        const float t = data[3 * k + 2];
        const float4 pi = zv[i];
        const float4 pj = zv[j];
        const float dx = fmaf(pi.z - pj.z, t, pi.x - pj.x);
        const float dy = fmaf(pi.w - pj.w, t, pi.y - pj.y);
        evt += b - fmaf(dx, dx, dy * dy);
    }

    // ---------------- block + grid reduction ----------------
    double tot = (double)evt - 0.88622692545275801 * (double)acc;

    #pragma unroll
    for (int off = 16; off > 0; off >>= 1)
        tot += __shfl_xor_sync(0xFFFFFFFFu, tot, off);

    __shared__ double wsum[THREADS / 32];
    __shared__ bool   s_last;
    const int wid = tid >> 5, lid = tid & 31;
    if (lid == 0) wsum[wid] = tot;
    __syncthreads();
    if (tid == 0) {
        double bs = 0.0;
        #pragma unroll
        for (int w = 0; w < THREADS / 32; w++) bs += wsum[w];
        g_part[bid] = bs;
        __threadfence();
        const unsigned v = atomicAdd(&g_flag, 1u);
        s_last = (v == (unsigned)(GRID - 1));
    }
    __syncthreads();

    if (s_last) {
        __threadfence();
        double sacc = (tid < GRID) ? g_part[tid] : 0.0;
        #pragma unroll
        for (int off = 16; off > 0; off >>= 1)
            sacc += __shfl_xor_sync(0xFFFFFFFFu, sacc, off);
        if (lid == 0) wsum[wid] = sacc;
        __syncthreads();
        if (tid == 0) {
            double fs = 0.0;
            #pragma unroll
            for (int w = 0; w < THREADS / 32; w++) fs += wsum[w];
            out[0] = (float)fs;
            g_flag = 0;   // reset for next replay
        }
    }
}

extern "C" void kernel_launch(void* const* d_in, const int* in_sizes, int n_in,
                              void* d_out, int out_size)
{
    // metadata order: data (M,3), t0, tn, beta (1,1), z0 (N,2), v0 (N,2)
    const float* data = (const float*)d_in[0];
    const float* t0   = (const float*)d_in[1];
    const float* tn   = (const float*)d_in[2];
    const float* beta = (const float*)d_in[3];
    const float* z0   = (const float*)d_in[4];
    const float* v0   = (const float*)d_in[5];

    const int M = in_sizes[0] / 3;
    const int N = in_sizes[4] / 2;

    const int smem = N * (int)sizeof(float4);   // 64 KB at N=4096
    static bool attr_set = false;
    if (!attr_set) {
        cudaFuncSetAttribute(fused_kernel,
                             cudaFuncAttributeMaxDynamicSharedMemorySize, smem);
        attr_set = true;
    }

    fused_kernel<<<GRID, THREADS, smem>>>(data, z0, v0, t0, tn, beta, N, M,
                                          (float*)d_out);
}

// round 12
// speedup vs baseline: 1.0931x; 1.0931x over previous
#include <cuda_runtime.h>
#include <math.h>

// -------------------------------------------------------------------------
// VectorizedConstantVelocityModel — GB300 sm_103a, round 12
//
// Base = R10 (best measured engine: 512 thr x 2 CTAs/SM, 2-row register
// tiling, coarse snake over 2048 row-pair units, cheap transcendentals,
// eps-fold, t0==0 specialization, evt prefetch, fused last-block reduction).
// R11's fine-grained snake reverted (it added ~4 inst/pair of overhead).
// New, isolated changes:
//  * #pragma unroll 2 on the inner j-loop (avg 4 trips) — halves loop
//    control, 4 independent pair chains in flight.
//  * dual accumulators acc0/acc1 (no serial FMA dependency between rows).
//  * erf_small with 4 minimax coefficients (abs err ~1e-5; |h| <= 0.71).
// -------------------------------------------------------------------------

#define THREADS 512
#define GRID    296

__device__ double       g_part[GRID];
__device__ unsigned int g_flag = 0;

__device__ __forceinline__ float ex2f(float x) {
    float r; asm("ex2.approx.f32 %0,%1;" : "=f"(r) : "f"(x)); return r;
}
__device__ __forceinline__ float rcpf(float x) {
    float r; asm("rcp.approx.f32 %0,%1;" : "=f"(r) : "f"(x)); return r;
}

#define L2E 1.4426950408889634f

// erf on [-0.75, 0.75]: odd poly, 4 coeffs (minimax-adjusted Taylor),
// abs err ~1e-5 on the needed range, no MUFU.
__device__ __forceinline__ float erf_small(float x)
{
    const float u = x * x;
    float p = fmaf(-0.0263211896f, u, 0.1126442985f);
    p = fmaf(p, u, -0.3761157195f);
    p = fmaf(p, u, 1.1283787672f);
    return x * p;
}

// erf for any x: A&S 7.1.25 (3-term), abs err ~2.5e-5, auto-saturating.
__device__ __forceinline__ float erf_any(float x)
{
    const float t = rcpf(fmaf(0.47047f, fabsf(x), 1.0f));   // MUFU.RCP
    float q = fmaf(0.7478556f, t, -0.0958798f);
    q = fmaf(q, t, 0.3480242f);
    q = q * t;
    const float ex = ex2f((-L2E * x) * x);   // exp(-x^2)
    return copysignf(fmaf(-q, ex, 1.0f), x);
}

// One pair (without sqrt(pi)/2): isq * exp(b + h^2 - c) * (erf(xu) - erf(xl))
template <bool T0Z>
__device__ __forceinline__ float pair_term(const float4 a4, const float4 b4,
                                           float bL2E, float t0, float tn)
{
    const float dzx = a4.x - b4.x;
    const float dzy = a4.y - b4.y;
    const float dvx = a4.z - b4.z;
    const float dvy = a4.w - b4.w;
    const float as  = fmaf(dvx, dvx, fmaf(dvy, dvy, 1e-10f));  // |dv|^2 + eps
    const float bbh = fmaf(dzx, dvx, dzy * dvy);               // dz.dv
    const float c   = fmaf(dzx, dzx, dzy * dzy);
    const float isq = rsqrtf(as);                              // MUFU.RSQ
    const float sqa = as * isq;
    const float h   = bbh * isq;                               // |h| <= 0.71
    const float t1   = fmaf(c, -L2E, bL2E);                    // (b - c)*log2e
    const float earg = fmaf(h * h, L2E, t1);
    const float eE   = ex2f(earg);                             // exp(b+h^2-c)
    const float xu = fmaf(sqa, tn, h);
    const float xl = T0Z ? h : fmaf(sqa, t0, h);
    const float dif = erf_any(xu) - erf_small(xl);
    return (isq * eE) * dif;
}

template <bool T0Z>
__device__ __forceinline__ float pair_loop(const float4* __restrict__ zv,
                                           int N, int bid, int tid,
                                           float bL2E, float t0, float tn)
{
    float acc0 = 0.0f, acc1 = 0.0f;
    const int NU = N >> 1;   // row-pair units (N even)

    for (int k = 0; ; k++) {
        const int u = (k & 1) ? ((k + 1) * GRID - 1 - bid) : (k * GRID + bid);
        if (u >= NU) break;

        const int i0 = 2 * u;
        const float4 a0 = zv[i0];
        const float4 a1 = zv[i0 + 1];

        if (tid == 0)   // boundary pair (i0, i0+1)
            acc0 += pair_term<T0Z>(a0, a1, bL2E, t0, tn);

        #pragma unroll 2
        for (int j = i0 + 2 + tid; j < N; j += THREADS) {
            const float4 b4 = zv[j];
            acc0 += pair_term<T0Z>(a0, b4, bL2E, t0, tn);
            acc1 += pair_term<T0Z>(a1, b4, bL2E, t0, tn);
        }
    }
    return acc0 + acc1;
}

__global__ __launch_bounds__(THREADS, 2)
void fused_kernel(const float* __restrict__ data,
                  const float* __restrict__ z0, const float* __restrict__ v0,
                  const float* __restrict__ t0p, const float* __restrict__ tnp,
                  const float* __restrict__ betap,
                  int N, int M, float* __restrict__ out)
{
    extern __shared__ float4 zv[];   // (zx, zy, vx, vy)
    const int tid = threadIdx.x;
    const int bid = blockIdx.x;

    const float t0 = t0p[0];
    const float tn = tnp[0];
    const float b  = betap[0];
    const float bL2E = b * L2E;

    // ---- prefetch this thread's event triple (<=1 event/thread here) ----
    const int k0 = bid * THREADS + tid;
    float efi = 0.0f, efj = 0.0f, eft = 0.0f;
    const bool has_evt = (k0 < M);
    if (has_evt) {
        efi = data[3 * k0 + 0];
        efj = data[3 * k0 + 1];
        eft = data[3 * k0 + 2];
    }

    // ---- build smem tile ----
    {
        const float2* z2 = (const float2*)z0;
        const float2* v2 = (const float2*)v0;
        for (int k = tid; k < N; k += THREADS) {
            const float2 z = z2[k], v = v2[k];
            zv[k] = make_float4(z.x, z.y, v.x, v.y);
        }
    }
    __syncthreads();

    // ---- pair term (dominant) ----
    float acc;
    if (t0 == 0.0f) acc = pair_loop<true >(zv, N, bid, tid, bL2E, t0, tn);
    else            acc = pair_loop<false>(zv, N, bid, tid, bL2E, t0, tn);

    // ---- event term (prefetched data, smem tile still resident) ----
    float evt = 0.0f;
    if (has_evt) {
        const int i = (int)efi;
        const int j = (int)efj;
        const float4 pi = zv[i];
        const float4 pj = zv[j];
        const float dx = fmaf(pi.z - pj.z, eft, pi.x - pj.x);
        const float dy = fmaf(pi.w - pj.w, eft, pi.y - pj.y);
        evt = b - fmaf(dx, dx, dy * dy);
    }
    for (int k = k0 + GRID * THREADS; k < M; k += GRID * THREADS) {
        const int   i = (int)data[3 * k + 0];
        const int   j = (int)data[3 * k + 1];
        const float t = data[3 * k + 2];
        const float4 pi = zv[i];
        const float4 pj = zv[j];
        const float dx = fmaf(pi.z - pj.z, t, pi.x - pj.x);
        const float dy = fmaf(pi.w - pj.w, t, pi.y - pj.y);
        evt += b - fmaf(dx, dx, dy * dy);
    }

    // ---------------- block + grid reduction ----------------
    double tot = (double)evt - 0.88622692545275801 * (double)acc;

    #pragma unroll
    for (int off = 16; off > 0; off >>= 1)
        tot += __shfl_xor_sync(0xFFFFFFFFu, tot, off);

    __shared__ double wsum[THREADS / 32];
    __shared__ bool   s_last;
    const int wid = tid >> 5, lid = tid & 31;
    if (lid == 0) wsum[wid] = tot;
    __syncthreads();
    if (tid == 0) {
        double bs = 0.0;
        #pragma unroll
        for (int w = 0; w < THREADS / 32; w++) bs += wsum[w];
        g_part[bid] = bs;
        __threadfence();
        const unsigned v = atomicAdd(&g_flag, 1u);
        s_last = (v == (unsigned)(GRID - 1));
    }
    __syncthreads();

    if (s_last) {
        __threadfence();
        double sacc = (tid < GRID) ? g_part[tid] : 0.0;
        #pragma unroll
        for (int off = 16; off > 0; off >>= 1)
            sacc += __shfl_xor_sync(0xFFFFFFFFu, sacc, off);
        if (lid == 0) wsum[wid] = sacc;
        __syncthreads();
        if (tid == 0) {
            double fs = 0.0;
            #pragma unroll
            for (int w = 0; w < THREADS / 32; w++) fs += wsum[w];
            out[0] = (float)fs;
            g_flag = 0;   // reset for next replay
        }
    }
}

extern "C" void kernel_launch(void* const* d_in, const int* in_sizes, int n_in,
                              void* d_out, int out_size)
{
    // metadata order: data (M,3), t0, tn, beta (1,1), z0 (N,2), v0 (N,2)
    const float* data = (const float*)d_in[0];
    const float* t0   = (const float*)d_in[1];
    const float* tn   = (const float*)d_in[2];
    const float* beta = (const float*)d_in[3];
    const float* z0   = (const float*)d_in[4];
    const float* v0   = (const float*)d_in[5];

    const int M = in_sizes[0] / 3;
    const int N = in_sizes[4] / 2;

    const int smem = N * (int)sizeof(float4);   // 64 KB at N=4096
    static bool attr_set = false;
    if (!attr_set) {
        cudaFuncSetAttribute(fused_kernel,
                             cudaFuncAttributeMaxDynamicSharedMemorySize, smem);
        attr_set = true;
    }

    fused_kernel<<<GRID, THREADS, smem>>>(data, z0, v0, t0, tn, beta, N, M,
                                          (float*)d_out);
}